// round 1
// baseline (speedup 1.0000x reference)
#include <cuda_runtime.h>
#include <cstdint>

// out[n] = S * ( sum_k (x[k]-X_ZP) * y[k,n]  -  Y_ZP * sum_k (x[k]-X_ZP) )
// with exact int32 accumulation (max magnitude ~1.58e8 < 2^31).
//
// X_SCALE=0.0215, X_ZP=-25, Y_SCALE=0.0176, Y_ZP=18

#define KDIM 8192
#define NDIM 16384
#define THREADS 256
#define COLS_PER_THREAD 4              // int4 per thread
#define COLS_PER_BLOCK (THREADS * COLS_PER_THREAD)   // 1024
#define N_TILES (NDIM / COLS_PER_BLOCK)              // 16
#define KCHUNK 128
#define KSPLITS (KDIM / KCHUNK)                      // 64

__device__ int g_acc[NDIM];
__device__ int g_sa;

__global__ void zero_kernel() {
    int i = blockIdx.x * blockDim.x + threadIdx.x;
    if (i < NDIM) g_acc[i] = 0;
    if (i == 0) g_sa = 0;
}

__global__ __launch_bounds__(THREADS) void gemv_kernel(
    const int* __restrict__ x, const int* __restrict__ y)
{
    __shared__ int sa[KCHUNK];
    const int tid = threadIdx.x;
    const int k0  = blockIdx.y * KCHUNK;

    // load x chunk, shift by zero point (a = x - X_ZP = x + 25)
    for (int i = tid; i < KCHUNK; i += THREADS)
        sa[i] = x[k0 + i] + 25;
    __syncthreads();

    const int n0 = blockIdx.x * COLS_PER_BLOCK + tid * COLS_PER_THREAD;
    const int4* yp = reinterpret_cast<const int4*>(
        y + (size_t)k0 * NDIM + n0);
    const size_t strideV = NDIM / 4;

    int ax = 0, ay = 0, az = 0, aw = 0;
    #pragma unroll 8
    for (int kk = 0; kk < KCHUNK; kk++) {
        const int a = sa[kk];
        const int4 v = yp[(size_t)kk * strideV];
        ax += a * v.x;
        ay += a * v.y;
        az += a * v.z;
        aw += a * v.w;
    }

    atomicAdd(&g_acc[n0 + 0], ax);
    atomicAdd(&g_acc[n0 + 1], ay);
    atomicAdd(&g_acc[n0 + 2], az);
    atomicAdd(&g_acc[n0 + 3], aw);

    // One n-tile contributes the Sa partial for this K chunk
    if (blockIdx.x == 0) {
        int s = (tid < KCHUNK) ? sa[tid] : 0;
        #pragma unroll
        for (int o = 16; o > 0; o >>= 1)
            s += __shfl_down_sync(0xffffffffu, s, o);
        if ((tid & 31) == 0) atomicAdd(&g_sa, s);
    }
}

__global__ void finalize_kernel(float* __restrict__ out) {
    int n = blockIdx.x * blockDim.x + threadIdx.x;
    if (n < NDIM) {
        const float S = (float)(0.0215 * 0.0176);
        out[n] = S * (float)(g_acc[n] - 18 * g_sa);
    }
}

extern "C" void kernel_launch(void* const* d_in, const int* in_sizes, int n_in,
                              void* d_out, int out_size) {
    const int* x = (const int*)d_in[0];   // [K]
    const int* y = (const int*)d_in[1];   // [K, N]
    float* out = (float*)d_out;           // [N]

    zero_kernel<<<(NDIM + THREADS - 1) / THREADS, THREADS>>>();

    dim3 grid(N_TILES, KSPLITS);
    gemv_kernel<<<grid, THREADS>>>(x, y);

    finalize_kernel<<<(NDIM + THREADS - 1) / THREADS, THREADS>>>(out);
}